// round 3
// baseline (speedup 1.0000x reference)
#include <cuda_runtime.h>

#define IH 384
#define IW 384
#define HO 382
#define WO 382
#define NB 8
#define HALO 6
#define TH 22          // rows [ho0-6, ho0+15]
#define TW 46          // cols [wo0-6, wo0+39]
#define TILE_CH (TH * TW)   // 1012

typedef unsigned long long u64;

__device__ __forceinline__ u64 fma2(u64 a, u64 b, u64 c) {
    u64 d; asm("fma.rn.f32x2 %0, %1, %2, %3;" : "=l"(d) : "l"(a), "l"(b), "l"(c)); return d;
}
__device__ __forceinline__ u64 pack2(float lo, float hi) {
    u64 r; asm("mov.b64 %0, {%1, %2};" : "=l"(r) : "f"(lo), "f"(hi)); return r;
}
__device__ __forceinline__ void unpack2(u64 v, float& lo, float& hi) {
    asm("mov.b64 {%0, %1}, %2;" : "=f"(lo), "=f"(hi) : "l"(v));
}

__global__ __launch_bounds__(128, 5)
void deform_fused3(const float* __restrict__ x,
                   const float* __restrict__ w1,
                   const float* __restrict__ b1,
                   const float* __restrict__ w2,
                   const float* __restrict__ b2,
                   float* __restrict__ out)
{
    __shared__ u64 s_tile[3 * TILE_CH];              // (x[i], x[i+1]) horizontal pairs, zero-filled
    __shared__ __align__(16) ulonglong2 s_w1q[9 * 28]; // per kk,j: (wdy,wdy | wdx,wdx)
    __shared__ u64 s_b1d[9], s_b1x[9];               // dup(b1_dy), dup(b1_dx)
    __shared__ u64 s_w2d[81];                        // dup(w2[o][c][kk]) at [o*27 + c*9 + kk]
    __shared__ u64 s_b2d[3];

    const int tid = threadIdx.y * 32 + threadIdx.x;

    // ---- weights to shared (packed/dup) ----
    for (int i = tid; i < 9 * 27; i += 128) {
        int kk = i / 27, j = i - kk * 27;
        float dyw = w1[(2 * kk) * 27 + j];
        float dxw = w1[(2 * kk + 1) * 27 + j];
        ulonglong2 q; q.x = pack2(dyw, dyw); q.y = pack2(dxw, dxw);
        s_w1q[kk * 28 + j] = q;
    }
    for (int i = tid; i < 9; i += 128) {
        float bdy = b1[2 * i], bdx = b1[2 * i + 1];
        s_b1d[i] = pack2(bdy, bdy);
        s_b1x[i] = pack2(bdx, bdx);
    }
    if (tid < 81) { float v = w2[tid]; s_w2d[tid] = pack2(v, v); }
    if (tid < 3)  { float v = b2[tid]; s_b2d[tid] = pack2(v, v); }

    const int wo0 = blockIdx.x * 32;
    const int ho0 = blockIdx.y * 8;
    const int b   = blockIdx.z;
    const float* __restrict__ xb = x + (size_t)b * 3 * IH * IW;

    const int rowBase = ho0 - HALO;
    const int colBase = wo0 - HALO;

    // ---- input tile: horizontal (x[i], x[i+1]) pairs, zero outside image ----
    for (int i = tid; i < 3 * TILE_CH; i += 128) {
        int c  = i / TILE_CH;
        int rr = i - c * TILE_CH;
        int r  = rr / TW;
        int col = rr - r * TW;
        int gy = rowBase + r;
        int gx = colBase + col;
        float lo = 0.f, hi = 0.f;
        if ((unsigned)gy < IH) {
            const float* rp = xb + ((size_t)c * IH + gy) * IW;
            if ((unsigned)gx < IW)       lo = __ldg(rp + gx);
            if ((unsigned)(gx + 1) < IW) hi = __ldg(rp + gx + 1);
        }
        s_tile[i] = pack2(lo, hi);
    }
    __syncthreads();

    const int wo  = wo0 + threadIdx.x;
    const int hoA = ho0 + 2 * threadIdx.y;       // pixel pair rows hoA, hoA+1
    const int ltx = threadIdx.x + HALO;
    const int lty = 2 * threadIdx.y + HALO;

    // ---- window as vertical pairs: wpair[c][r][kw] = (row lty+r, row lty+r+1), r=0..2 ----
    u64 wpair[27];
#pragma unroll
    for (int c = 0; c < 3; c++)
#pragma unroll
        for (int r = 0; r < 3; r++)
#pragma unroll
            for (int kw = 0; kw < 3; kw++) {
                float t0, t1, hidum;
                unpack2(s_tile[c * TILE_CH + (lty + r) * TW + (ltx + kw)], t0, hidum);
                unpack2(s_tile[c * TILE_CH + (lty + r + 1) * TW + (ltx + kw)], t1, hidum);
                wpair[c * 9 + r * 3 + kw] = pack2(t0, t1);
            }

    u64 accp[3];
#pragma unroll
    for (int o = 0; o < 3; o++) accp[o] = s_b2d[o];

#pragma unroll 1
    for (int kk = 0; kk < 9; kk++) {
        // ---- offset conv: (dy_p0, dy_p1) and (dx_p0, dx_p1) via f32x2 ----
        u64 ady = s_b1d[kk];
        u64 adx = s_b1x[kk];
        const ulonglong2* __restrict__ wq = &s_w1q[kk * 28];
#pragma unroll
        for (int j = 0; j < 27; j++) {
            ulonglong2 w = wq[j];
            u64 wp = wpair[j];
            ady = fma2(wp, w.x, ady);
            adx = fma2(wp, w.y, adx);
        }

        const int kh = kk / 3;
        const int kw = kk - 3 * kh;

        float dy0, dy1, dx0, dx1;
        unpack2(ady, dy0, dy1);
        unpack2(adx, dx0, dx1);

        float vch[2][3];
#pragma unroll
        for (int p = 0; p < 2; p++) {
            float dy = p ? dy1 : dy0;
            float dx = p ? dx1 : dx0;
            float py = (float)(hoA + p + kh) + dy;
            float px = (float)(wo + kw) + dx;
            float fy0 = floorf(py);
            float fx0 = floorf(px);
            float wy = py - fy0;
            float wx = px - fx0;
            int y0 = (int)fy0;
            int x0 = (int)fx0;
            int ly0 = y0 - rowBase;
            int lx0 = x0 - colBase;

            float c00 = (1.f - wy) * (1.f - wx);
            float c01 = (1.f - wy) * wx;
            float c10 = wy * (1.f - wx);
            float c11 = wy * wx;

            if ((unsigned)ly0 <= TH - 2 && (unsigned)lx0 <= TW - 2) {
                // fast path: zero-filled tile makes validity masks redundant
                int t = ly0 * TW + lx0;
#pragma unroll
                for (int c = 0; c < 3; c++) {
                    float t0, t1, b0, b1v;
                    unpack2(s_tile[c * TILE_CH + t], t0, t1);
                    unpack2(s_tile[c * TILE_CH + t + TW], b0, b1v);
                    float v = c00 * t0;
                    v = fmaf(c01, t1, v);
                    v = fmaf(c10, b0, v);
                    v = fmaf(c11, b1v, v);
                    vch[p][c] = v;
                }
            } else {
                // rare slow path: exact reference semantics (clamp + validity)
                bool vy0 = (y0 >= 0)  && (y0 <= IH - 1);
                bool vy1 = (y0 >= -1) && (y0 <= IH - 2);
                bool vx0 = (x0 >= 0)  && (x0 <= IW - 1);
                bool vx1 = (x0 >= -1) && (x0 <= IW - 2);
                float m00 = c00 * ((vy0 && vx0) ? 1.f : 0.f);
                float m01 = c01 * ((vy0 && vx1) ? 1.f : 0.f);
                float m10 = c10 * ((vy1 && vx0) ? 1.f : 0.f);
                float m11 = c11 * ((vy1 && vx1) ? 1.f : 0.f);
                int yc0 = min(max(y0, 0), IH - 1);
                int yc1 = min(max(y0 + 1, 0), IH - 1);
                int xc0 = min(max(x0, 0), IW - 1);
                int xc1 = min(max(x0 + 1, 0), IW - 1);
                int i00 = yc0 * IW + xc0;
                int i01 = yc0 * IW + xc1;
                int i10 = yc1 * IW + xc0;
                int i11 = yc1 * IW + xc1;
#pragma unroll
                for (int c = 0; c < 3; c++) {
                    const float* __restrict__ xc = xb + (size_t)c * IH * IW;
                    vch[p][c] = m00 * __ldg(xc + i00) + m01 * __ldg(xc + i01)
                              + m10 * __ldg(xc + i10) + m11 * __ldg(xc + i11);
                }
            }
        }

        // ---- accumulate both pixels together: acc[o] += dup(w2[o][c][kk]) * (v0,v1) ----
#pragma unroll
        for (int c = 0; c < 3; c++) {
            u64 vp = pack2(vch[0][c], vch[1][c]);
            accp[0] = fma2(s_w2d[0 * 27 + c * 9 + kk], vp, accp[0]);
            accp[1] = fma2(s_w2d[1 * 27 + c * 9 + kk], vp, accp[1]);
            accp[2] = fma2(s_w2d[2 * 27 + c * 9 + kk], vp, accp[2]);
        }
    }

    // ---- store ----
    if (wo < WO) {
        const size_t plane = (size_t)HO * WO;
        float a0, a1;
#pragma unroll
        for (int o = 0; o < 3; o++) {
            unpack2(accp[o], a0, a1);
            if (hoA < HO) out[(size_t)b * 3 * plane + (size_t)o * plane + (size_t)hoA * WO + wo] = a0;
            if (hoA + 1 < HO) out[(size_t)b * 3 * plane + (size_t)o * plane + (size_t)(hoA + 1) * WO + wo] = a1;
        }
    }
}

extern "C" void kernel_launch(void* const* d_in, const int* in_sizes, int n_in,
                              void* d_out, int out_size)
{
    const float* x  = (const float*)d_in[0];
    const float* w1 = (const float*)d_in[1];
    const float* b1 = (const float*)d_in[2];
    const float* w2 = (const float*)d_in[3];
    const float* b2 = (const float*)d_in[4];
    float* out = (float*)d_out;

    cudaFuncSetAttribute(deform_fused3, cudaFuncAttributePreferredSharedMemoryCarveout, 100);

    dim3 block(32, 4, 1);
    dim3 grid((WO + 31) / 32, (HO + 7) / 8, NB);
    deform_fused3<<<grid, block>>>(x, w1, b1, w2, b2, out);
}